// round 6
// baseline (speedup 1.0000x reference)
#include <cuda_runtime.h>
#include <math.h>

#define L 256
#define D 300
#define D4 75          // D/4
#define S 16
#define KK 16
#define C 7
#define NS 48          // 3*S
#define DH 150         // D/2
#define TM 16          // row tile for 300-wide GEMMs
#define TMF 8          // row tile for fuse GEMM (900-wide input)

// ---------------- scratch (device globals; no allocation) ----------------
__device__ float g_P0[L*D];
__device__ float g_P1[L*D];
__device__ float g_Q[L*D];
__device__ float g_Kb[L*D];
__device__ float g_Vb[L*D];
__device__ float g_hidden[L*D];
__device__ float g_A[L*D];
__device__ float g_relatt[L*D];
__device__ float g_h1[L*D];
__device__ float g_norm[L];
__device__ float g_nodes[L*NS*D];   // 14.7 MB
__device__ int   g_nodemask[L*NS];
__device__ float g_sym[L*D];

__device__ __forceinline__ float warp_sum(float v) {
    #pragma unroll
    for (int o = 16; o; o >>= 1) v += __shfl_down_sync(0xffffffffu, v, o);
    return v;
}

// ---------------- K1: six GEMMs, register-blocked over TM rows -----------
__global__ void gemm6_kernel(const float* __restrict__ x,
                             const float* __restrict__ Wbasis,
                             const float* __restrict__ Wself,
                             const float* __restrict__ brgcn,
                             const float* __restrict__ Wq,
                             const float* __restrict__ Wk,
                             const float* __restrict__ Wv) {
    int tile = blockIdx.x, m = blockIdx.y, j = threadIdx.x;
    int l0 = tile * TM;
    __shared__ float xs[TM][D];
    for (int i = threadIdx.x; i < TM*D; i += blockDim.x) {
        int r = i / D, d = i - r*D;
        xs[r][d] = x[(l0 + r)*D + d];
    }
    __syncthreads();
    if (j >= D) return;
    const float* W; float* out;
    switch (m) {
        case 0: W = Wbasis;        out = g_P0;     break;
        case 1: W = Wbasis + D*D;  out = g_P1;     break;
        case 2: W = Wself;         out = g_hidden; break;
        case 3: W = Wq;            out = g_Q;      break;
        case 4: W = Wk;            out = g_Kb;     break;
        default:W = Wv;            out = g_Vb;     break;
    }
    float acc[TM];
    #pragma unroll
    for (int r = 0; r < TM; r++) acc[r] = 0.f;
    #pragma unroll 2
    for (int k = 0; k < D; k++) {
        float w = W[k*D + j];
        #pragma unroll
        for (int r = 0; r < TM; r++) acc[r] = fmaf(xs[r][k], w, acc[r]);
    }
    float b = (m == 2) ? brgcn[j] : 0.f;
    #pragma unroll
    for (int r = 0; r < TM; r++) out[(l0 + r)*D + j] = acc[r] + b;
}

// ---------------- K2: RGCN edge scatter via basis decomposition ----------
__global__ void edge_kernel(const int* __restrict__ src,
                            const int* __restrict__ dst,
                            const int* __restrict__ etype,
                            const float* __restrict__ comp) {
    int e = blockIdx.x, j = threadIdx.x;
    if (j >= D) return;
    int r = etype[e];
    float c0 = comp[2*r], c1 = comp[2*r + 1];
    int s = src[e], d = dst[e];
    float v = fmaf(c0, g_P0[s*D + j], c1 * g_P1[s*D + j]);
    atomicAdd(&g_hidden[d*D + j], v);
}

// ---------------- K3: windowed 2-head attention (only center query) ------
__global__ void attn_kernel() {
    int l = blockIdx.x;
    int tid = threadIdx.x, warp = tid >> 5, lane = tid & 31;
    __shared__ float lg[2][3];
    __shared__ float p[2][3];
    int w0 = (l == 0) ? 0 : l - 1;
    int w2 = (l == L-1) ? L-1 : l + 1;
    int win[3] = {w0, l, w2};
    if (warp < 6) {
        int h = warp / 3, j = warp % 3;
        const float* q = g_Q  + l*D       + h*DH;
        const float* k = g_Kb + win[j]*D  + h*DH;
        float acc = 0.f;
        for (int d = lane; d < DH; d += 32) acc += q[d] * k[d];
        acc = warp_sum(acc);
        if (lane == 0) lg[h][j] = acc * 0.08164965809277261f;  // 1/sqrt(150)
    }
    __syncthreads();
    if (tid < 2) {
        float m = fmaxf(lg[tid][0], fmaxf(lg[tid][1], lg[tid][2]));
        float e0 = expf(lg[tid][0]-m), e1 = expf(lg[tid][1]-m), e2 = expf(lg[tid][2]-m);
        float inv = 1.f / (e0 + e1 + e2);
        p[tid][0] = e0*inv; p[tid][1] = e1*inv; p[tid][2] = e2*inv;
    }
    __syncthreads();
    for (int t = tid; t < D; t += blockDim.x) {
        int h = t / DH, d = t - h*DH;
        float acc = p[h][0] * g_Vb[win[0]*D + h*DH + d]
                  + p[h][1] * g_Vb[win[1]*D + h*DH + d]
                  + p[h][2] * g_Vb[win[2]*D + h*DH + d];
        g_A[l*D + t] = acc;
    }
}

// ---------------- K4: relatt = A @ Wo, register-blocked ------------------
__global__ void wo_kernel(const float* __restrict__ Wo) {
    int tile = blockIdx.x, j = threadIdx.x;
    int l0 = tile * TM;
    __shared__ float xs[TM][D];
    for (int i = threadIdx.x; i < TM*D; i += blockDim.x) {
        int r = i / D, d = i - r*D;
        xs[r][d] = g_A[(l0 + r)*D + d];
    }
    __syncthreads();
    if (j >= D) return;
    float acc[TM];
    #pragma unroll
    for (int r = 0; r < TM; r++) acc[r] = 0.f;
    #pragma unroll 2
    for (int k = 0; k < D; k++) {
        float w = Wo[k*D + j];
        #pragma unroll
        for (int r = 0; r < TM; r++) acc[r] = fmaf(xs[r][k], w, acc[r]);
    }
    #pragma unroll
    for (int r = 0; r < TM; r++) g_relatt[(l0 + r)*D + j] = acc[r];
}

// ---------------- K4b: row norms of relatt -------------------------------
__global__ void norm_kernel() {
    int l = blockIdx.x, tid = threadIdx.x;   // 128 threads
    __shared__ float red[4];
    float s = 0.f;
    for (int d = tid; d < D; d += 128) {
        float v = g_relatt[l*D + d];
        s = fmaf(v, v, s);
    }
    s = warp_sum(s);
    int warp = tid >> 5, lane = tid & 31;
    if (lane == 0) red[warp] = s;
    __syncthreads();
    if (tid == 0)
        g_norm[l] = sqrtf(red[0] + red[1] + red[2] + red[3]);
}

// ---------------- K5: concept-graph attention (float4 gather) ------------
__global__ void concept_kernel(const int* __restrict__ src_ids,
                               const int* __restrict__ dst_ids,
                               const float* __restrict__ wgt,
                               const float* __restrict__ sentic,
                               const float* __restrict__ table,
                               const float* __restrict__ rvecs) {
    int bid = blockIdx.x;                 // g*L*S + l*S + s
    int g = bid / (L*S);
    int rem = bid - g*(L*S);
    int l = rem / S;
    int s = rem - l*S;
    int n = g*S + s;
    int tid = threadIdx.x;                // 256 threads, 8 warps

    __shared__ float4 sh_dst[KK][D4];
    __shared__ float4 sh_src[D4], sh_u[D4], sh_r[D4];
    __shared__ float sh_du[KK], sh_dd[KK], sh_ds[KK], sh_c[KK];
    __shared__ int   sh_ids[KK];

    int src_id = src_ids[bid];
    float4* outrow = (float4*)&g_nodes[(size_t)(l*NS + n) * D];
    if (src_id < 0) {
        if (tid == 0) g_nodemask[l*NS + n] = 0;
        float4 z = make_float4(0.f, 0.f, 0.f, 0.f);
        if (tid < D4) outrow[tid] = z;
        return;
    }
    if (tid == 0) g_nodemask[l*NS + n] = 1;
    if (tid < KK) sh_ids[tid] = dst_ids[(size_t)bid*KK + tid];
    if (tid < D4) {
        sh_src[tid] = ((const float4*)(table + (size_t)src_id*D))[tid];
        sh_u[tid]   = ((const float4*)(g_relatt + l*D))[tid];
        sh_r[tid]   = ((const float4*)(rvecs + g*D))[tid];
    }
    __syncthreads();

    int warp = tid >> 5, lane = tid & 31;
    #pragma unroll
    for (int kit = 0; kit < 2; kit++) {
        int k = warp + kit*8;
        int id = sh_ids[k];
        float du = 0.f, dd = 0.f, ds = 0.f;
        if (id >= 0) {
            const float4* row = (const float4*)(table + (size_t)id*D);
            for (int d = lane; d < D4; d += 32) {
                float4 v = row[d];
                sh_dst[k][d] = v;
                float4 u = sh_u[d], sr = sh_src[d], rr = sh_r[d];
                du = fmaf(u.x, v.x, fmaf(u.y, v.y, fmaf(u.z, v.z, fmaf(u.w, v.w, du))));
                dd = fmaf(v.x, v.x, fmaf(v.y, v.y, fmaf(v.z, v.z, fmaf(v.w, v.w, dd))));
                ds = fmaf(sr.x*rr.x, v.x, fmaf(sr.y*rr.y, v.y,
                     fmaf(sr.z*rr.z, v.z, fmaf(sr.w*rr.w, v.w, ds))));
            }
            du = warp_sum(du); dd = warp_sum(dd); ds = warp_sum(ds);
        } else {
            float4 z = make_float4(0.f, 0.f, 0.f, 0.f);
            for (int d = lane; d < D4; d += 32) sh_dst[k][d] = z;
        }
        if (lane == 0) { sh_du[k] = du; sh_dd[k] = dd; sh_ds[k] = ds; }
    }
    __syncthreads();

    if (tid == 0) {
        float norm_u = g_norm[l];
        float om[KK], a1[KK], sv[KK], a2[KK];
        float m1 = -1e30f; int anyv = 0;
        for (int k = 0; k < KK; k++) {
            if (sh_ids[k] >= 0) {
                float cosv = fabsf(sh_du[k]) / (norm_u * sqrtf(sh_dd[k]) + 1e-8f);
                float w  = wgt[(size_t)bid*KK + k];
                float sn = sentic[(size_t)bid*KK + k];
                om[k] = 0.5f*w*cosv + 0.5f*fabsf(sn);
                if (om[k] > m1) m1 = om[k];
                anyv = 1;
            } else om[k] = 0.f;
        }
        float sum1 = 0.f;
        for (int k = 0; k < KK; k++) {
            a1[k] = (sh_ids[k] >= 0) ? expf(om[k] - m1) : 0.f;
            sum1 += a1[k];
        }
        float inv1 = anyv ? (1.f / sum1) : 0.f;
        float m2 = -1e30f;
        for (int k = 0; k < KK; k++) {
            a1[k] *= inv1;
            sv[k] = a1[k] * sh_ds[k];
            if (sh_ids[k] >= 0 && sv[k] > m2) m2 = sv[k];
        }
        float sum2 = 0.f;
        for (int k = 0; k < KK; k++) {
            a2[k] = (sh_ids[k] >= 0) ? expf(sv[k] - m2) : 0.f;
            sum2 += a2[k];
        }
        float inv2 = anyv ? (1.f / sum2) : 0.f;
        for (int k = 0; k < KK; k++) sh_c[k] = a1[k] * a2[k] * inv2;
    }
    __syncthreads();

    if (tid < D4) {
        float ax = 0.f, ay = 0.f, az = 0.f, aw = 0.f;
        #pragma unroll
        for (int k = 0; k < KK; k++) {
            float c = sh_c[k];
            float4 v = sh_dst[k][tid];
            ax = fmaf(c, v.x, ax); ay = fmaf(c, v.y, ay);
            az = fmaf(c, v.z, az); aw = fmaf(c, v.w, aw);
        }
        float4 sr = sh_src[tid], rr = sh_r[tid], o;
        o.x = fmaf(rr.x, ax, sr.x); o.y = fmaf(rr.y, ay, sr.y);
        o.z = fmaf(rr.z, az, sr.z); o.w = fmaf(rr.w, aw, sr.w);
        outrow[tid] = o;
    }
}

// ---------------- K6: symbolic attention over 48 nodes (float4) ----------
__global__ void sym_kernel() {
    int l = blockIdx.x, tid = threadIdx.x;   // 256 threads
    __shared__ float4 sh_u[D4];
    __shared__ float score[NS];
    __shared__ float att[NS];
    __shared__ float s_any;
    if (tid < D4) sh_u[tid] = ((const float4*)(g_relatt + l*D))[tid];
    __syncthreads();
    int warp = tid >> 5, lane = tid & 31;
    #pragma unroll
    for (int it = 0; it < 6; it++) {
        int nn = warp + it*8;
        float acc = 0.f;
        if (g_nodemask[l*NS + nn]) {
            const float4* row = (const float4*)&g_nodes[(size_t)(l*NS + nn) * D];
            for (int d = lane; d < D4; d += 32) {
                float4 v = row[d], u = sh_u[d];
                acc = fmaf(v.x, u.x, fmaf(v.y, u.y, fmaf(v.z, u.z, fmaf(v.w, u.w, acc))));
            }
            acc = warp_sum(acc);
        }
        if (lane == 0) score[nn] = acc;
    }
    __syncthreads();
    if (tid == 0) {
        float m = -1e30f; int anyv = 0;
        for (int nn = 0; nn < NS; nn++)
            if (g_nodemask[l*NS + nn]) { if (score[nn] > m) m = score[nn]; anyv = 1; }
        float sum = 0.f;
        for (int nn = 0; nn < NS; nn++) {
            att[nn] = g_nodemask[l*NS + nn] ? expf(score[nn] - m) : 0.f;
            sum += att[nn];
        }
        float inv = anyv ? (1.f / sum) : 0.f;
        for (int nn = 0; nn < NS; nn++) att[nn] *= inv;
        s_any = anyv ? 1.f : 0.f;
    }
    __syncthreads();
    if (tid < D4) {
        float ax = 0.f, ay = 0.f, az = 0.f, aw = 0.f;
        for (int nn = 0; nn < NS; nn++) {
            float a = att[nn];
            float4 v = ((const float4*)&g_nodes[(size_t)(l*NS + nn) * D])[tid];
            ax = fmaf(a, v.x, ax); ay = fmaf(a, v.y, ay);
            az = fmaf(a, v.z, az); aw = fmaf(a, v.w, aw);
        }
        float any = s_any;
        float4 o = make_float4(ax*any, ay*any, az*any, aw*any);
        ((float4*)(g_sym + l*D))[tid] = o;
    }
}

// ---------------- K7a: fuse GEMM (900x300), register-blocked -------------
__global__ void fuse1_kernel(const float* __restrict__ Wf,
                             const float* __restrict__ bf) {
    int tile = blockIdx.x, j = threadIdx.x;   // 320 threads
    int l0 = tile * TMF;
    __shared__ float feat[TMF][3*D];
    for (int i = threadIdx.x; i < TMF*D; i += blockDim.x) {
        int r = i / D, d = i - r*D;
        feat[r][d]       = g_hidden[(l0 + r)*D + d];
        feat[r][D + d]   = g_relatt[(l0 + r)*D + d];
        feat[r][2*D + d] = g_sym[(l0 + r)*D + d];
    }
    __syncthreads();
    if (j >= D) return;
    float acc[TMF];
    float b = bf[j];
    #pragma unroll
    for (int r = 0; r < TMF; r++) acc[r] = b;
    #pragma unroll 2
    for (int i = 0; i < 3*D; i++) {
        float w = Wf[i*D + j];
        #pragma unroll
        for (int r = 0; r < TMF; r++) acc[r] = fmaf(feat[r][i], w, acc[r]);
    }
    #pragma unroll
    for (int r = 0; r < TMF; r++) g_h1[(l0 + r)*D + j] = fmaxf(acc[r], 0.f);
}

// ---------------- K7b: logits + log_softmax ------------------------------
__global__ void fuse2_kernel(const float* __restrict__ Wout,
                             const float* __restrict__ bout,
                             float* __restrict__ out) {
    int l = blockIdx.x, tid = threadIdx.x;   // 256 threads
    __shared__ float logits[C];
    __shared__ float sh_lse;
    int warp = tid >> 5, lane = tid & 31;
    if (warp < C) {
        float acc = 0.f;
        for (int j = lane; j < D; j += 32)
            acc = fmaf(g_h1[l*D + j], Wout[j*C + warp], acc);
        acc = warp_sum(acc);
        if (lane == 0) logits[warp] = acc + bout[warp];
    }
    __syncthreads();
    if (tid == 0) {
        float m = logits[0];
        #pragma unroll
        for (int c = 1; c < C; c++) m = fmaxf(m, logits[c]);
        float sum = 0.f;
        #pragma unroll
        for (int c = 0; c < C; c++) sum += expf(logits[c] - m);
        sh_lse = m + logf(sum);
    }
    __syncthreads();
    if (tid < C) out[l*C + tid] = logits[tid] - sh_lse;
}

// ---------------- launch --------------------------------------------------
extern "C" void kernel_launch(void* const* d_in, const int* in_sizes, int n_in,
                              void* d_out, int out_size) {
    const float* utt    = (const float*)d_in[0];
    const int*   ssrc   = (const int*)  d_in[1];
    const int*   sdst   = (const int*)  d_in[2];
    const int*   setype = (const int*)  d_in[3];
    const int*   csrc   = (const int*)  d_in[4];
    const int*   cdst   = (const int*)  d_in[5];
    const float* cw     = (const float*)d_in[6];
    const float* cs     = (const float*)d_in[7];
    const float* table  = (const float*)d_in[8];
    const float* Wbasis = (const float*)d_in[9];
    const float* comp   = (const float*)d_in[10];
    const float* Wself  = (const float*)d_in[11];
    const float* brgcn  = (const float*)d_in[12];
    const float* Wq     = (const float*)d_in[13];
    const float* Wk     = (const float*)d_in[14];
    const float* Wv     = (const float*)d_in[15];
    const float* Wo     = (const float*)d_in[16];
    const float* rvecs  = (const float*)d_in[17];
    const float* Wf     = (const float*)d_in[18];
    const float* bf     = (const float*)d_in[19];
    const float* Wout   = (const float*)d_in[20];
    const float* bout   = (const float*)d_in[21];
    float* out = (float*)d_out;

    int n_edges = in_sizes[1];

    gemm6_kernel<<<dim3(L/TM, 6), 320>>>(utt, Wbasis, Wself, brgcn, Wq, Wk, Wv);
    edge_kernel<<<n_edges, 300>>>(ssrc, sdst, setype, comp);
    attn_kernel<<<L, 192>>>();
    wo_kernel<<<L/TM, 320>>>(Wo);
    norm_kernel<<<L, 128>>>();
    concept_kernel<<<3*L*S, 256>>>(csrc, cdst, cw, cs, table, rvecs);
    sym_kernel<<<L, 256>>>();
    fuse1_kernel<<<L/TMF, 320>>>(Wf, bf);
    fuse2_kernel<<<L, 256>>>(Wout, bout, out);
}

// round 9
// speedup vs baseline: 1.2278x; 1.2278x over previous
#include <cuda_runtime.h>
#include <math.h>

#define L 256
#define D 300
#define D4 75          // D/4
#define S 16
#define KK 16
#define C 7
#define NS 48          // 3*S
#define DH 150         // D/2
#define TM 8           // row tile for 300-wide GEMMs
#define TMF 4          // row tile for fuse GEMM

// ---------------- scratch (device globals; no allocation) ----------------
__device__ float g_P0[L*D];
__device__ float g_P1[L*D];
__device__ float g_Q[L*D];
__device__ float g_Kb[L*D];
__device__ float g_VO0[L*D];
__device__ float g_VO1[L*D];
__device__ float g_Wvo[2][D*D];
__device__ float g_hidden[L*D];
__device__ float g_relatt[L*D];
__device__ float g_h1[L*D];
__device__ float g_norm[L];
__device__ float g_nodes[L*NS*D];   // 14.7 MB
__device__ int   g_nodemask[L*NS];
__device__ float g_sym[L*D];

__device__ __forceinline__ float warp_sum(float v) {
    #pragma unroll
    for (int o = 16; o; o >>= 1) v += __shfl_down_sync(0xffffffffu, v, o);
    return v;
}

// ---------------- K0: Wvo_h = Wv_h @ Wo_h  (300x150x300, per head) -------
__global__ void wvo_kernel(const float* __restrict__ Wv,
                           const float* __restrict__ Wo) {
    int tile = blockIdx.x, h = blockIdx.y, j = threadIdx.x;
    int r0 = tile * TM;
    __shared__ float xs[TM][DH];
    for (int i = threadIdx.x; i < TM*DH; i += blockDim.x) {
        int r = i / DH, d = i - r*DH;
        int row = r0 + r;
        xs[r][d] = (row < D) ? Wv[row*D + h*DH + d] : 0.f;
    }
    __syncthreads();
    if (j >= D) return;
    float acc[TM];
    #pragma unroll
    for (int r = 0; r < TM; r++) acc[r] = 0.f;
    #pragma unroll 4
    for (int d = 0; d < DH; d++) {
        float w = Wo[(h*DH + d)*D + j];
        #pragma unroll
        for (int r = 0; r < TM; r++) acc[r] = fmaf(xs[r][d], w, acc[r]);
    }
    #pragma unroll
    for (int r = 0; r < TM; r++)
        if (r0 + r < D) g_Wvo[h][(r0 + r)*D + j] = acc[r];
}

// ---------------- K1: seven GEMMs out = utt @ W, TM rows, 224 blocks -----
__global__ void gemm7_kernel(const float* __restrict__ x,
                             const float* __restrict__ Wbasis,
                             const float* __restrict__ Wself,
                             const float* __restrict__ brgcn,
                             const float* __restrict__ Wq,
                             const float* __restrict__ Wk) {
    int tile = blockIdx.x, m = blockIdx.y, j = threadIdx.x;
    int l0 = tile * TM;
    __shared__ float xs[TM][D];
    for (int i = threadIdx.x; i < TM*D; i += blockDim.x) {
        int r = i / D, d = i - r*D;
        xs[r][d] = x[(l0 + r)*D + d];
    }
    __syncthreads();
    if (j >= D) return;
    const float* W; float* out;
    switch (m) {
        case 0: W = Wbasis;        out = g_P0;     break;
        case 1: W = Wbasis + D*D;  out = g_P1;     break;
        case 2: W = Wself;         out = g_hidden; break;
        case 3: W = Wq;            out = g_Q;      break;
        case 4: W = Wk;            out = g_Kb;     break;
        case 5: W = g_Wvo[0];      out = g_VO0;    break;
        default:W = g_Wvo[1];      out = g_VO1;    break;
    }
    float acc[TM];
    #pragma unroll
    for (int r = 0; r < TM; r++) acc[r] = 0.f;
    #pragma unroll 4
    for (int k = 0; k < D; k++) {
        float w = W[k*D + j];
        #pragma unroll
        for (int r = 0; r < TM; r++) acc[r] = fmaf(xs[r][k], w, acc[r]);
    }
    float b = (m == 2) ? brgcn[j] : 0.f;
    #pragma unroll
    for (int r = 0; r < TM; r++) out[(l0 + r)*D + j] = acc[r] + b;
}

// ---------------- K2: RGCN edge scatter via basis decomposition ----------
__global__ void edge_kernel(const int* __restrict__ src,
                            const int* __restrict__ dst,
                            const int* __restrict__ etype,
                            const float* __restrict__ comp) {
    int e = blockIdx.x, j = threadIdx.x;
    if (j >= D) return;
    int r = etype[e];
    float c0 = comp[2*r], c1 = comp[2*r + 1];
    int s = src[e], d = dst[e];
    float v = fmaf(c0, g_P0[s*D + j], c1 * g_P1[s*D + j]);
    atomicAdd(&g_hidden[d*D + j], v);
}

// ---------------- K3: windowed attn -> relatt directly (+ norms) ---------
__global__ void attn_kernel() {
    int l = blockIdx.x;
    int tid = threadIdx.x, warp = tid >> 5, lane = tid & 31;   // 192 thr
    __shared__ float lg[2][3];
    __shared__ float p[2][3];
    __shared__ float red[6];
    int w0 = (l == 0) ? 0 : l - 1;
    int w2 = (l == L-1) ? L-1 : l + 1;
    int win[3] = {w0, l, w2};
    if (warp < 6) {
        int h = warp / 3, j = warp % 3;
        const float* q = g_Q  + l*D       + h*DH;
        const float* k = g_Kb + win[j]*D  + h*DH;
        float acc = 0.f;
        for (int d = lane; d < DH; d += 32) acc += q[d] * k[d];
        acc = warp_sum(acc);
        if (lane == 0) lg[h][j] = acc * 0.08164965809277261f;  // 1/sqrt(150)
    }
    __syncthreads();
    if (tid < 2) {
        float m = fmaxf(lg[tid][0], fmaxf(lg[tid][1], lg[tid][2]));
        float e0 = expf(lg[tid][0]-m), e1 = expf(lg[tid][1]-m), e2 = expf(lg[tid][2]-m);
        float inv = 1.f / (e0 + e1 + e2);
        p[tid][0] = e0*inv; p[tid][1] = e1*inv; p[tid][2] = e2*inv;
    }
    __syncthreads();
    float nrm = 0.f;
    for (int d = tid; d < D; d += 192) {
        float acc = 0.f;
        #pragma unroll
        for (int j = 0; j < 3; j++) {
            acc = fmaf(p[0][j], g_VO0[win[j]*D + d], acc);
            acc = fmaf(p[1][j], g_VO1[win[j]*D + d], acc);
        }
        g_relatt[l*D + d] = acc;
        nrm = fmaf(acc, acc, nrm);
    }
    nrm = warp_sum(nrm);
    if (lane == 0) red[warp] = nrm;
    __syncthreads();
    if (tid == 0) {
        float t = red[0] + red[1] + red[2] + red[3] + red[4] + red[5];
        g_norm[l] = sqrtf(t);
    }
}

// ---------------- K5: concept-graph attention (float4 gather) ------------
__global__ void concept_kernel(const int* __restrict__ src_ids,
                               const int* __restrict__ dst_ids,
                               const float* __restrict__ wgt,
                               const float* __restrict__ sentic,
                               const float* __restrict__ table,
                               const float* __restrict__ rvecs) {
    int bid = blockIdx.x;                 // g*L*S + l*S + s
    int g = bid / (L*S);
    int rem = bid - g*(L*S);
    int l = rem / S;
    int s = rem - l*S;
    int n = g*S + s;
    int tid = threadIdx.x;                // 256 threads, 8 warps

    __shared__ float4 sh_dst[KK][D4];
    __shared__ float4 sh_src[D4], sh_u[D4], sh_r[D4];
    __shared__ float sh_du[KK], sh_dd[KK], sh_ds[KK], sh_c[KK];
    __shared__ int   sh_ids[KK];

    int src_id = src_ids[bid];
    float4* outrow = (float4*)&g_nodes[(size_t)(l*NS + n) * D];
    if (src_id < 0) {
        if (tid == 0) g_nodemask[l*NS + n] = 0;
        float4 z = make_float4(0.f, 0.f, 0.f, 0.f);
        if (tid < D4) outrow[tid] = z;
        return;
    }
    if (tid == 0) g_nodemask[l*NS + n] = 1;
    if (tid < KK) sh_ids[tid] = dst_ids[(size_t)bid*KK + tid];
    if (tid < D4) {
        sh_src[tid] = ((const float4*)(table + (size_t)src_id*D))[tid];
        sh_u[tid]   = ((const float4*)(g_relatt + l*D))[tid];
        sh_r[tid]   = ((const float4*)(rvecs + g*D))[tid];
    }
    __syncthreads();

    int warp = tid >> 5, lane = tid & 31;
    #pragma unroll
    for (int kit = 0; kit < 2; kit++) {
        int k = warp + kit*8;
        int id = sh_ids[k];
        float du = 0.f, dd = 0.f, ds = 0.f;
        if (id >= 0) {
            const float4* row = (const float4*)(table + (size_t)id*D);
            for (int d = lane; d < D4; d += 32) {
                float4 v = row[d];
                sh_dst[k][d] = v;
                float4 u = sh_u[d], sr = sh_src[d], rr = sh_r[d];
                du = fmaf(u.x, v.x, fmaf(u.y, v.y, fmaf(u.z, v.z, fmaf(u.w, v.w, du))));
                dd = fmaf(v.x, v.x, fmaf(v.y, v.y, fmaf(v.z, v.z, fmaf(v.w, v.w, dd))));
                ds = fmaf(sr.x*rr.x, v.x, fmaf(sr.y*rr.y, v.y,
                     fmaf(sr.z*rr.z, v.z, fmaf(sr.w*rr.w, v.w, ds))));
            }
            du = warp_sum(du); dd = warp_sum(dd); ds = warp_sum(ds);
        } else {
            float4 z = make_float4(0.f, 0.f, 0.f, 0.f);
            for (int d = lane; d < D4; d += 32) sh_dst[k][d] = z;
        }
        if (lane == 0) { sh_du[k] = du; sh_dd[k] = dd; sh_ds[k] = ds; }
    }
    __syncthreads();

    if (tid == 0) {
        float norm_u = g_norm[l];
        float om[KK], a1[KK], sv[KK], a2[KK];
        float m1 = -1e30f; int anyv = 0;
        for (int k = 0; k < KK; k++) {
            if (sh_ids[k] >= 0) {
                float cosv = fabsf(sh_du[k]) / (norm_u * sqrtf(sh_dd[k]) + 1e-8f);
                float w  = wgt[(size_t)bid*KK + k];
                float sn = sentic[(size_t)bid*KK + k];
                om[k] = 0.5f*w*cosv + 0.5f*fabsf(sn);
                if (om[k] > m1) m1 = om[k];
                anyv = 1;
            } else om[k] = 0.f;
        }
        float sum1 = 0.f;
        for (int k = 0; k < KK; k++) {
            a1[k] = (sh_ids[k] >= 0) ? expf(om[k] - m1) : 0.f;
            sum1 += a1[k];
        }
        float inv1 = anyv ? (1.f / sum1) : 0.f;
        float m2 = -1e30f;
        for (int k = 0; k < KK; k++) {
            a1[k] *= inv1;
            sv[k] = a1[k] * sh_ds[k];
            if (sh_ids[k] >= 0 && sv[k] > m2) m2 = sv[k];
        }
        float sum2 = 0.f;
        for (int k = 0; k < KK; k++) {
            a2[k] = (sh_ids[k] >= 0) ? expf(sv[k] - m2) : 0.f;
            sum2 += a2[k];
        }
        float inv2 = anyv ? (1.f / sum2) : 0.f;
        for (int k = 0; k < KK; k++) sh_c[k] = a1[k] * a2[k] * inv2;
    }
    __syncthreads();

    if (tid < D4) {
        float ax = 0.f, ay = 0.f, az = 0.f, aw = 0.f;
        #pragma unroll
        for (int k = 0; k < KK; k++) {
            float c = sh_c[k];
            float4 v = sh_dst[k][tid];
            ax = fmaf(c, v.x, ax); ay = fmaf(c, v.y, ay);
            az = fmaf(c, v.z, az); aw = fmaf(c, v.w, aw);
        }
        float4 sr = sh_src[tid], rr = sh_r[tid], o;
        o.x = fmaf(rr.x, ax, sr.x); o.y = fmaf(rr.y, ay, sr.y);
        o.z = fmaf(rr.z, az, sr.z); o.w = fmaf(rr.w, aw, sr.w);
        outrow[tid] = o;
    }
}

// ---------------- K6: symbolic attention over 48 nodes (float4) ----------
__global__ void sym_kernel() {
    int l = blockIdx.x, tid = threadIdx.x;   // 256 threads
    __shared__ float4 sh_u[D4];
    __shared__ float score[NS];
    __shared__ float att[NS];
    __shared__ float s_any;
    if (tid < D4) sh_u[tid] = ((const float4*)(g_relatt + l*D))[tid];
    __syncthreads();
    int warp = tid >> 5, lane = tid & 31;
    #pragma unroll
    for (int it = 0; it < 6; it++) {
        int nn = warp + it*8;
        float acc = 0.f;
        if (g_nodemask[l*NS + nn]) {
            const float4* row = (const float4*)&g_nodes[(size_t)(l*NS + nn) * D];
            for (int d = lane; d < D4; d += 32) {
                float4 v = row[d], u = sh_u[d];
                acc = fmaf(v.x, u.x, fmaf(v.y, u.y, fmaf(v.z, u.z, fmaf(v.w, u.w, acc))));
            }
            acc = warp_sum(acc);
        }
        if (lane == 0) score[nn] = acc;
    }
    __syncthreads();
    if (tid == 0) {
        float m = -1e30f; int anyv = 0;
        for (int nn = 0; nn < NS; nn++)
            if (g_nodemask[l*NS + nn]) { if (score[nn] > m) m = score[nn]; anyv = 1; }
        float sum = 0.f;
        for (int nn = 0; nn < NS; nn++) {
            att[nn] = g_nodemask[l*NS + nn] ? expf(score[nn] - m) : 0.f;
            sum += att[nn];
        }
        float inv = anyv ? (1.f / sum) : 0.f;
        for (int nn = 0; nn < NS; nn++) att[nn] *= inv;
        s_any = anyv ? 1.f : 0.f;
    }
    __syncthreads();
    if (tid < D4) {
        float ax = 0.f, ay = 0.f, az = 0.f, aw = 0.f;
        for (int nn = 0; nn < NS; nn++) {
            float a = att[nn];
            float4 v = ((const float4*)&g_nodes[(size_t)(l*NS + nn) * D])[tid];
            ax = fmaf(a, v.x, ax); ay = fmaf(a, v.y, ay);
            az = fmaf(a, v.z, az); aw = fmaf(a, v.w, aw);
        }
        float any = s_any;
        float4 o = make_float4(ax*any, ay*any, az*any, aw*any);
        ((float4*)(g_sym + l*D))[tid] = o;
    }
}

// ---------------- K7a: fuse GEMM (900x300), row-block + col-split --------
__global__ void fuse1_kernel(const float* __restrict__ Wf,
                             const float* __restrict__ bf) {
    int tile = blockIdx.x, cs = blockIdx.y, tid = threadIdx.x;  // 160 thr
    int l0 = tile * TMF;
    int j = cs * DH + tid;
    __shared__ float feat[TMF][3*D];
    for (int i = tid; i < TMF*D; i += blockDim.x) {
        int r = i / D, d = i - r*D;
        feat[r][d]       = g_hidden[(l0 + r)*D + d];
        feat[r][D + d]   = g_relatt[(l0 + r)*D + d];
        feat[r][2*D + d] = g_sym[(l0 + r)*D + d];
    }
    __syncthreads();
    if (tid >= DH) return;
    float acc[TMF];
    float b = bf[j];
    #pragma unroll
    for (int r = 0; r < TMF; r++) acc[r] = b;
    #pragma unroll 4
    for (int i = 0; i < 3*D; i++) {
        float w = Wf[i*D + j];
        #pragma unroll
        for (int r = 0; r < TMF; r++) acc[r] = fmaf(feat[r][i], w, acc[r]);
    }
    #pragma unroll
    for (int r = 0; r < TMF; r++) g_h1[(l0 + r)*D + j] = fmaxf(acc[r], 0.f);
}

// ---------------- K7b: logits + log_softmax ------------------------------
__global__ void fuse2_kernel(const float* __restrict__ Wout,
                             const float* __restrict__ bout,
                             float* __restrict__ out) {
    int l = blockIdx.x, tid = threadIdx.x;   // 256 threads
    __shared__ float logits[C];
    __shared__ float sh_lse;
    int warp = tid >> 5, lane = tid & 31;
    if (warp < C) {
        float acc = 0.f;
        for (int j = lane; j < D; j += 32)
            acc = fmaf(g_h1[l*D + j], Wout[j*C + warp], acc);
        acc = warp_sum(acc);
        if (lane == 0) logits[warp] = acc + bout[warp];
    }
    __syncthreads();
    if (tid == 0) {
        float m = logits[0];
        #pragma unroll
        for (int c = 1; c < C; c++) m = fmaxf(m, logits[c]);
        float sum = 0.f;
        #pragma unroll
        for (int c = 0; c < C; c++) sum += expf(logits[c] - m);
        sh_lse = m + logf(sum);
    }
    __syncthreads();
    if (tid < C) out[l*C + tid] = logits[tid] - sh_lse;
}

// ---------------- launch --------------------------------------------------
extern "C" void kernel_launch(void* const* d_in, const int* in_sizes, int n_in,
                              void* d_out, int out_size) {
    const float* utt    = (const float*)d_in[0];
    const int*   ssrc   = (const int*)  d_in[1];
    const int*   sdst   = (const int*)  d_in[2];
    const int*   setype = (const int*)  d_in[3];
    const int*   csrc   = (const int*)  d_in[4];
    const int*   cdst   = (const int*)  d_in[5];
    const float* cw     = (const float*)d_in[6];
    const float* cs     = (const float*)d_in[7];
    const float* table  = (const float*)d_in[8];
    const float* Wbasis = (const float*)d_in[9];
    const float* comp   = (const float*)d_in[10];
    const float* Wself  = (const float*)d_in[11];
    const float* brgcn  = (const float*)d_in[12];
    const float* Wq     = (const float*)d_in[13];
    const float* Wk     = (const float*)d_in[14];
    const float* Wv     = (const float*)d_in[15];
    const float* Wo     = (const float*)d_in[16];
    const float* rvecs  = (const float*)d_in[17];
    const float* Wf     = (const float*)d_in[18];
    const float* bf     = (const float*)d_in[19];
    const float* Wout   = (const float*)d_in[20];
    const float* bout   = (const float*)d_in[21];
    float* out = (float*)d_out;

    int n_edges = in_sizes[1];

    wvo_kernel<<<dim3((D + TM - 1)/TM, 2), 320>>>(Wv, Wo);
    gemm7_kernel<<<dim3(L/TM, 7), 320>>>(utt, Wbasis, Wself, brgcn, Wq, Wk);
    edge_kernel<<<n_edges, 300>>>(ssrc, sdst, setype, comp);
    attn_kernel<<<L, 192>>>();
    concept_kernel<<<3*L*S, 256>>>(csrc, cdst, cw, cs, table, rvecs);
    sym_kernel<<<L, 256>>>();
    fuse1_kernel<<<dim3(L/TMF, 2), 160>>>(Wf, bf);
    fuse2_kernel<<<L, 256>>>(Wout, bout, out);
}

// round 11
// speedup vs baseline: 2.7575x; 2.2459x over previous
#include <cuda_runtime.h>
#include <math.h>

#define L 256
#define D 300
#define D4 75          // D/4
#define S 16
#define KK 16
#define C 7
#define NS 48          // 3*S
#define DH 150         // D/2
#define TM 4           // row tile for 300-wide GEMMs
#define TMF 4          // row tile for fuse GEMM

// ---------------- scratch (device globals; no allocation) ----------------
__device__ float g_P0[L*D];
__device__ float g_P1[L*D];
__device__ float g_Q[L*D];
__device__ float g_Kb[L*D];
__device__ float g_VO0[L*D];
__device__ float g_VO1[L*D];
__device__ float g_Wvo[2][D*D];
__device__ float g_hidden[L*D];
__device__ float g_relatt[L*D];
__device__ float g_h1p[3][L*D];
__device__ float g_norm[L];
__device__ float g_nodes[L*NS*D];   // 14.7 MB
__device__ int   g_nodemask[L*NS];
__device__ float g_sym[L*D];

__device__ __forceinline__ float warp_sum(float v) {
    #pragma unroll
    for (int o = 16; o; o >>= 1) v += __shfl_down_sync(0xffffffffu, v, o);
    return v;
}
__device__ __forceinline__ float warp_max(float v) {
    #pragma unroll
    for (int o = 16; o; o >>= 1) v = fmaxf(v, __shfl_xor_sync(0xffffffffu, v, o));
    return v;
}
__device__ __forceinline__ float warp_sum_x(float v) {
    #pragma unroll
    for (int o = 16; o; o >>= 1) v += __shfl_xor_sync(0xffffffffu, v, o);
    return v;
}

// ---------------- K0: Wvo_h = Wv_h @ Wo_h  (300x150x300, per head) -------
__global__ void __launch_bounds__(320) wvo_kernel(const float* __restrict__ Wv,
                                                  const float* __restrict__ Wo) {
    int tile = blockIdx.x, h = blockIdx.y, j = threadIdx.x;
    int r0 = tile * TM;
    __shared__ float xs[TM][DH];
    for (int i = threadIdx.x; i < TM*DH; i += blockDim.x) {
        int r = i / DH, d = i - r*DH;
        int row = r0 + r;
        xs[r][d] = (row < D) ? Wv[row*D + h*DH + d] : 0.f;
    }
    __syncthreads();
    if (j >= D) return;
    float acc[TM];
    #pragma unroll
    for (int r = 0; r < TM; r++) acc[r] = 0.f;
    #pragma unroll 8
    for (int d = 0; d < DH; d++) {
        float w = Wo[(h*DH + d)*D + j];
        #pragma unroll
        for (int r = 0; r < TM; r++) acc[r] = fmaf(xs[r][d], w, acc[r]);
    }
    #pragma unroll
    for (int r = 0; r < TM; r++)
        if (r0 + r < D) g_Wvo[h][(r0 + r)*D + j] = acc[r];
}

// ---------------- K1: seven GEMMs out = utt @ W, TM=4 rows, 448 blocks ---
__global__ void __launch_bounds__(320) gemm7_kernel(const float* __restrict__ x,
                             const float* __restrict__ Wbasis,
                             const float* __restrict__ Wself,
                             const float* __restrict__ brgcn,
                             const float* __restrict__ Wq,
                             const float* __restrict__ Wk) {
    int tile = blockIdx.x, m = blockIdx.y, j = threadIdx.x;
    int l0 = tile * TM;
    __shared__ float xs[TM][D];
    for (int i = threadIdx.x; i < TM*D; i += blockDim.x) {
        int r = i / D, d = i - r*D;
        xs[r][d] = x[(l0 + r)*D + d];
    }
    __syncthreads();
    if (j >= D) return;
    const float* W; float* out;
    switch (m) {
        case 0: W = Wbasis;        out = g_P0;     break;
        case 1: W = Wbasis + D*D;  out = g_P1;     break;
        case 2: W = Wself;         out = g_hidden; break;
        case 3: W = Wq;            out = g_Q;      break;
        case 4: W = Wk;            out = g_Kb;     break;
        case 5: W = g_Wvo[0];      out = g_VO0;    break;
        default:W = g_Wvo[1];      out = g_VO1;    break;
    }
    float acc[TM];
    #pragma unroll
    for (int r = 0; r < TM; r++) acc[r] = 0.f;
    #pragma unroll 8
    for (int k = 0; k < D; k++) {
        float w = W[k*D + j];
        #pragma unroll
        for (int r = 0; r < TM; r++) acc[r] = fmaf(xs[r][k], w, acc[r]);
    }
    float b = (m == 2) ? brgcn[j] : 0.f;
    #pragma unroll
    for (int r = 0; r < TM; r++) out[(l0 + r)*D + j] = acc[r] + b;
}

// ---------------- K2: RGCN edge scatter via basis decomposition ----------
__global__ void edge_kernel(const int* __restrict__ src,
                            const int* __restrict__ dst,
                            const int* __restrict__ etype,
                            const float* __restrict__ comp) {
    int e = blockIdx.x, j = threadIdx.x;
    if (j >= D) return;
    int r = etype[e];
    float c0 = comp[2*r], c1 = comp[2*r + 1];
    int s = src[e], d = dst[e];
    float v = fmaf(c0, g_P0[s*D + j], c1 * g_P1[s*D + j]);
    atomicAdd(&g_hidden[d*D + j], v);
}

// ---------------- K3: windowed attn -> relatt directly (+ norms) ---------
__global__ void attn_kernel() {
    int l = blockIdx.x;
    int tid = threadIdx.x, warp = tid >> 5, lane = tid & 31;   // 192 thr
    __shared__ float lg[2][3];
    __shared__ float p[2][3];
    __shared__ float red[6];
    int w0 = (l == 0) ? 0 : l - 1;
    int w2 = (l == L-1) ? L-1 : l + 1;
    int win[3] = {w0, l, w2};
    if (warp < 6) {
        int h = warp / 3, j = warp % 3;
        const float* q = g_Q  + l*D       + h*DH;
        const float* k = g_Kb + win[j]*D  + h*DH;
        float acc = 0.f;
        for (int d = lane; d < DH; d += 32) acc += q[d] * k[d];
        acc = warp_sum(acc);
        if (lane == 0) lg[h][j] = acc * 0.08164965809277261f;  // 1/sqrt(150)
    }
    __syncthreads();
    if (tid < 2) {
        float m = fmaxf(lg[tid][0], fmaxf(lg[tid][1], lg[tid][2]));
        float e0 = expf(lg[tid][0]-m), e1 = expf(lg[tid][1]-m), e2 = expf(lg[tid][2]-m);
        float inv = 1.f / (e0 + e1 + e2);
        p[tid][0] = e0*inv; p[tid][1] = e1*inv; p[tid][2] = e2*inv;
    }
    __syncthreads();
    float nrm = 0.f;
    for (int d = tid; d < D; d += 192) {
        float acc = 0.f;
        #pragma unroll
        for (int j = 0; j < 3; j++) {
            acc = fmaf(p[0][j], g_VO0[win[j]*D + d], acc);
            acc = fmaf(p[1][j], g_VO1[win[j]*D + d], acc);
        }
        g_relatt[l*D + d] = acc;
        nrm = fmaf(acc, acc, nrm);
    }
    nrm = warp_sum(nrm);
    if (lane == 0) red[warp] = nrm;
    __syncthreads();
    if (tid == 0) {
        float t = red[0] + red[1] + red[2] + red[3] + red[4] + red[5];
        g_norm[l] = sqrtf(t);
    }
}

// ---------------- K5: concept-graph attention ----------------------------
// per (g,l,s) block: dual-row gather per warp (MLP x2), warp-parallel softmax
__global__ void concept_kernel(const int* __restrict__ src_ids,
                               const int* __restrict__ dst_ids,
                               const float* __restrict__ wgt,
                               const float* __restrict__ sentic,
                               const float* __restrict__ table,
                               const float* __restrict__ rvecs) {
    int bid = blockIdx.x;                 // g*L*S + l*S + s
    int g = bid / (L*S);
    int rem = bid - g*(L*S);
    int l = rem / S;
    int s = rem - l*S;
    int n = g*S + s;
    int tid = threadIdx.x;                // 256 threads, 8 warps

    __shared__ float4 sh_dst[KK][D4];
    __shared__ float4 sh_src[D4], sh_u[D4], sh_r[D4];
    __shared__ float sh_du[KK], sh_dd[KK], sh_ds[KK], sh_c[KK];
    __shared__ int   sh_ids[KK];

    int src_id = src_ids[bid];
    float4* outrow = (float4*)&g_nodes[(size_t)(l*NS + n) * D];
    if (src_id < 0) {
        if (tid == 0) g_nodemask[l*NS + n] = 0;
        float4 z = make_float4(0.f, 0.f, 0.f, 0.f);
        if (tid < D4) outrow[tid] = z;
        return;
    }
    if (tid == 0) g_nodemask[l*NS + n] = 1;
    if (tid < KK) sh_ids[tid] = dst_ids[(size_t)bid*KK + tid];
    if (tid < D4) {
        sh_src[tid] = ((const float4*)(table + (size_t)src_id*D))[tid];
        sh_u[tid]   = ((const float4*)(g_relatt + l*D))[tid];
        sh_r[tid]   = ((const float4*)(rvecs + g*D))[tid];
    }
    __syncthreads();

    int warp = tid >> 5, lane = tid & 31;
    {
        int k0 = warp, k1 = warp + 8;
        int id0 = sh_ids[k0], id1 = sh_ids[k1];
        const float4* row0 = (const float4*)(table + (size_t)(id0 < 0 ? 0 : id0)*D);
        const float4* row1 = (const float4*)(table + (size_t)(id1 < 0 ? 0 : id1)*D);
        float du0=0.f, dd0=0.f, ds0=0.f, du1=0.f, dd1=0.f, ds1=0.f;
        float4 z = make_float4(0.f, 0.f, 0.f, 0.f);
        for (int d = lane; d < D4; d += 32) {
            float4 v0 = (id0 >= 0) ? row0[d] : z;
            float4 v1 = (id1 >= 0) ? row1[d] : z;
            sh_dst[k0][d] = v0;
            sh_dst[k1][d] = v1;
            float4 u = sh_u[d], sr = sh_src[d], rr = sh_r[d];
            float px = sr.x*rr.x, py = sr.y*rr.y, pz = sr.z*rr.z, pw = sr.w*rr.w;
            du0 = fmaf(u.x, v0.x, fmaf(u.y, v0.y, fmaf(u.z, v0.z, fmaf(u.w, v0.w, du0))));
            dd0 = fmaf(v0.x, v0.x, fmaf(v0.y, v0.y, fmaf(v0.z, v0.z, fmaf(v0.w, v0.w, dd0))));
            ds0 = fmaf(px, v0.x, fmaf(py, v0.y, fmaf(pz, v0.z, fmaf(pw, v0.w, ds0))));
            du1 = fmaf(u.x, v1.x, fmaf(u.y, v1.y, fmaf(u.z, v1.z, fmaf(u.w, v1.w, du1))));
            dd1 = fmaf(v1.x, v1.x, fmaf(v1.y, v1.y, fmaf(v1.z, v1.z, fmaf(v1.w, v1.w, dd1))));
            ds1 = fmaf(px, v1.x, fmaf(py, v1.y, fmaf(pz, v1.z, fmaf(pw, v1.w, ds1))));
        }
        du0 = warp_sum(du0); dd0 = warp_sum(dd0); ds0 = warp_sum(ds0);
        du1 = warp_sum(du1); dd1 = warp_sum(dd1); ds1 = warp_sum(ds1);
        if (lane == 0) {
            sh_du[k0] = du0; sh_dd[k0] = dd0; sh_ds[k0] = ds0;
            sh_du[k1] = du1; sh_dd[k1] = dd1; sh_ds[k1] = ds1;
        }
    }
    __syncthreads();

    // warp-parallel double softmax (warp 0, lane = k)
    if (warp == 0) {
        int k = lane;
        bool valid = (k < KK) && (sh_ids[k] >= 0);
        float norm_u = g_norm[l];
        float om = -1e30f;
        if (valid) {
            float cosv = fabsf(sh_du[k]) / (norm_u * sqrtf(sh_dd[k]) + 1e-8f);
            float w  = wgt[(size_t)bid*KK + k];
            float sn = sentic[(size_t)bid*KK + k];
            om = 0.5f*w*cosv + 0.5f*fabsf(sn);
        }
        float m1 = warp_max(om);
        float a1 = valid ? expf(om - m1) : 0.f;
        float sum1 = warp_sum_x(a1);
        a1 *= (sum1 > 0.f) ? (1.f / sum1) : 0.f;
        float sv = valid ? a1 * sh_ds[k] : -1e30f;
        float m2 = warp_max(sv);
        float a2 = valid ? expf(sv - m2) : 0.f;
        float sum2 = warp_sum_x(a2);
        float c = a1 * a2 * ((sum2 > 0.f) ? (1.f / sum2) : 0.f);
        if (k < KK) sh_c[k] = c;
    }
    __syncthreads();

    if (tid < D4) {
        float ax = 0.f, ay = 0.f, az = 0.f, aw = 0.f;
        #pragma unroll
        for (int k = 0; k < KK; k++) {
            float c = sh_c[k];
            float4 v = sh_dst[k][tid];
            ax = fmaf(c, v.x, ax); ay = fmaf(c, v.y, ay);
            az = fmaf(c, v.z, az); aw = fmaf(c, v.w, aw);
        }
        float4 sr = sh_src[tid], rr = sh_r[tid], o;
        o.x = fmaf(rr.x, ax, sr.x); o.y = fmaf(rr.y, ay, sr.y);
        o.z = fmaf(rr.z, az, sr.z); o.w = fmaf(rr.w, aw, sr.w);
        outrow[tid] = o;
    }
}

// ---------------- K6: symbolic attention over 48 nodes (float4) ----------
__global__ void sym_kernel() {
    int l = blockIdx.x, tid = threadIdx.x;   // 256 threads
    __shared__ float4 sh_u[D4];
    __shared__ float score[NS];
    __shared__ float att[NS];
    __shared__ float s_any;
    if (tid < D4) sh_u[tid] = ((const float4*)(g_relatt + l*D))[tid];
    __syncthreads();
    int warp = tid >> 5, lane = tid & 31;
    #pragma unroll
    for (int it = 0; it < 6; it++) {
        int nn = warp + it*8;
        float acc = 0.f;
        if (g_nodemask[l*NS + nn]) {
            const float4* row = (const float4*)&g_nodes[(size_t)(l*NS + nn) * D];
            for (int d = lane; d < D4; d += 32) {
                float4 v = row[d], u = sh_u[d];
                acc = fmaf(v.x, u.x, fmaf(v.y, u.y, fmaf(v.z, u.z, fmaf(v.w, u.w, acc))));
            }
            acc = warp_sum(acc);
        }
        if (lane == 0) score[nn] = acc;
    }
    __syncthreads();
    if (tid == 0) {
        float m = -1e30f; int anyv = 0;
        for (int nn = 0; nn < NS; nn++)
            if (g_nodemask[l*NS + nn]) { if (score[nn] > m) m = score[nn]; anyv = 1; }
        float sum = 0.f;
        for (int nn = 0; nn < NS; nn++) {
            att[nn] = g_nodemask[l*NS + nn] ? expf(score[nn] - m) : 0.f;
            sum += att[nn];
        }
        float inv = anyv ? (1.f / sum) : 0.f;
        for (int nn = 0; nn < NS; nn++) att[nn] *= inv;
        s_any = anyv ? 1.f : 0.f;
    }
    __syncthreads();
    if (tid < D4) {
        float ax = 0.f, ay = 0.f, az = 0.f, aw = 0.f;
        for (int nn = 0; nn < NS; nn++) {
            float a = att[nn];
            float4 v = ((const float4*)&g_nodes[(size_t)(l*NS + nn) * D])[tid];
            ax = fmaf(a, v.x, ax); ay = fmaf(a, v.y, ay);
            az = fmaf(a, v.z, az); aw = fmaf(a, v.w, aw);
        }
        float any = s_any;
        float4 o = make_float4(ax*any, ay*any, az*any, aw*any);
        ((float4*)(g_sym + l*D))[tid] = o;
    }
}

// ---------------- K7a: fuse GEMM split-K: each z-block does one source ---
__global__ void __launch_bounds__(160) fuse1_kernel(const float* __restrict__ Wf) {
    int tile = blockIdx.x, cs = blockIdx.y, ks = blockIdx.z;
    int tid = threadIdx.x;   // 160 threads
    int l0 = tile * TMF;
    const float* srcbuf = (ks == 0) ? g_hidden : (ks == 1) ? g_relatt : g_sym;
    __shared__ float xs[TMF][D];
    for (int i = tid; i < TMF*D; i += blockDim.x) {
        int r = i / D, d = i - r*D;
        xs[r][d] = srcbuf[(l0 + r)*D + d];
    }
    __syncthreads();
    if (tid >= DH) return;
    int j = cs * DH + tid;
    const float* W = Wf + (size_t)(ks*D)*D;    // rows [ks*300, ks*300+300)
    float acc[TMF];
    #pragma unroll
    for (int r = 0; r < TMF; r++) acc[r] = 0.f;
    #pragma unroll 8
    for (int k = 0; k < D; k++) {
        float w = W[k*D + j];
        #pragma unroll
        for (int r = 0; r < TMF; r++) acc[r] = fmaf(xs[r][k], w, acc[r]);
    }
    #pragma unroll
    for (int r = 0; r < TMF; r++) g_h1p[ks][(l0 + r)*D + j] = acc[r];
}

// ---------------- K7b: combine partials + relu + logits + log_softmax ----
__global__ void fuse2_kernel(const float* __restrict__ bf,
                             const float* __restrict__ Wout,
                             const float* __restrict__ bout,
                             float* __restrict__ out) {
    int l = blockIdx.x, tid = threadIdx.x;   // 256 threads
    __shared__ float logits[C];
    __shared__ float sh_lse;
    int warp = tid >> 5, lane = tid & 31;
    if (warp < C) {
        float acc = 0.f;
        for (int j = lane; j < D; j += 32) {
            float h = g_h1p[0][l*D + j] + g_h1p[1][l*D + j] + g_h1p[2][l*D + j] + bf[j];
            h = fmaxf(h, 0.f);
            acc = fmaf(h, Wout[j*C + warp], acc);
        }
        acc = warp_sum(acc);
        if (lane == 0) logits[warp] = acc + bout[warp];
    }
    __syncthreads();
    if (tid == 0) {
        float m = logits[0];
        #pragma unroll
        for (int c = 1; c < C; c++) m = fmaxf(m, logits[c]);
        float sum = 0.f;
        #pragma unroll
        for (int c = 0; c < C; c++) sum += expf(logits[c] - m);
        sh_lse = m + logf(sum);
    }
    __syncthreads();
    if (tid < C) out[l*C + tid] = logits[tid] - sh_lse;
}

// ---------------- launch --------------------------------------------------
extern "C" void kernel_launch(void* const* d_in, const int* in_sizes, int n_in,
                              void* d_out, int out_size) {
    const float* utt    = (const float*)d_in[0];
    const int*   ssrc   = (const int*)  d_in[1];
    const int*   sdst   = (const int*)  d_in[2];
    const int*   setype = (const int*)  d_in[3];
    const int*   csrc   = (const int*)  d_in[4];
    const int*   cdst   = (const int*)  d_in[5];
    const float* cw     = (const float*)d_in[6];
    const float* cs     = (const float*)d_in[7];
    const float* table  = (const float*)d_in[8];
    const float* Wbasis = (const float*)d_in[9];
    const float* comp   = (const float*)d_in[10];
    const float* Wself  = (const float*)d_in[11];
    const float* brgcn  = (const float*)d_in[12];
    const float* Wq     = (const float*)d_in[13];
    const float* Wk     = (const float*)d_in[14];
    const float* Wv     = (const float*)d_in[15];
    const float* Wo     = (const float*)d_in[16];
    const float* rvecs  = (const float*)d_in[17];
    const float* Wf     = (const float*)d_in[18];
    const float* bf     = (const float*)d_in[19];
    const float* Wout   = (const float*)d_in[20];
    const float* bout   = (const float*)d_in[21];
    float* out = (float*)d_out;

    int n_edges = in_sizes[1];

    wvo_kernel<<<dim3((D + TM - 1)/TM, 2), 320>>>(Wv, Wo);
    gemm7_kernel<<<dim3(L/TM, 7), 320>>>(utt, Wbasis, Wself, brgcn, Wq, Wk);
    edge_kernel<<<n_edges, 300>>>(ssrc, sdst, setype, comp);
    attn_kernel<<<L, 192>>>();
    concept_kernel<<<3*L*S, 256>>>(csrc, cdst, cw, cs, table, rvecs);
    sym_kernel<<<L, 256>>>();
    fuse1_kernel<<<dim3(L/TMF, 2, 3), 160>>>(Wf);
    fuse2_kernel<<<L, 256>>>(bf, Wout, bout, out);
}